// round 2
// baseline (speedup 1.0000x reference)
#include <cuda_runtime.h>
#include <math.h>

// ---------------- problem constants ----------------
#define Bb     2
#define Ss     2048
#define DIMc   2048
#define Hh     16
#define QLORA  1536
#define KVLORA 512
#define NOPEc  128
#define ROPEc  64
#define VDIMc  128
#define QKH    192            // NOPE + ROPE
#define ROWS   (Bb*Ss)        // 4096
#define DF     576            // 512 latent + 64 rope
#define SCALEc 0.07216878364870322f  // 1/sqrt(192)
#define EPSc   1e-6f

// ---------------- scratch (static device arrays; no allocation) ----------------
__device__ float g_qlat[(size_t)ROWS * QLORA];          // 4096 x 1536
__device__ float g_q[(size_t)ROWS * (Hh * QKH)];        // 4096 x 3072
__device__ float g_kv[(size_t)ROWS * DF];               // 4096 x 576 (raw kv_a output)
__device__ float g_kfull[(size_t)ROWS * DF];            // 4096 x 576 (normed latent + roped kpe)
__device__ float g_qfull[(size_t)ROWS * Hh * DF];       // 4096 x 16 x 576 (absorbed q + roped qpe)
__device__ float g_ctx[(size_t)ROWS * Hh * KVLORA];     // 4096 x 16 x 512
__device__ float g_attnout[(size_t)ROWS * DIMc];        // 4096 x 2048

// ---------------- generic tiled fp32 GEMM ----------------
// C[M,N] = A[M,K] @ op(B). TB=true: B is [N,K] row-major (C = A B^T).
//                           TB=false: B is [K,N] row-major (C = A B).
// Batched over grid.z with element strides sA/sB/sC.
#define GBM 128
#define GBN 128
#define GBK 8

template<bool TB>
__global__ __launch_bounds__(256) void gemm_kernel(
    const float* __restrict__ A, int lda, long sA,
    const float* __restrict__ B, int ldb, long sB,
    float* __restrict__ C, int ldc, long sC,
    int M, int N, int K)
{
    __shared__ float As[GBK][GBM + 4];
    __shared__ float Bs[GBK][GBN + 4];

    int z = blockIdx.z;
    A += (size_t)z * sA;
    B += (size_t)z * sB;
    C += (size_t)z * sC;

    int tid = threadIdx.x;
    int m0 = blockIdx.y * GBM;
    int n0 = blockIdx.x * GBN;
    int ti = tid >> 4;        // 0..15 row group
    int tj = tid & 15;        // 0..15 col group

    int lrow = tid >> 1;      // 0..127
    int lk   = (tid & 1) * 4; // 0 or 4

    float acc[8][8];
#pragma unroll
    for (int i = 0; i < 8; i++)
#pragma unroll
        for (int j = 0; j < 8; j++) acc[i][j] = 0.f;

    for (int k0 = 0; k0 < K; k0 += GBK) {
        // load A tile (transpose into As[k][m])
        {
            float4 av = *(const float4*)(A + (size_t)(m0 + lrow) * lda + k0 + lk);
            As[lk + 0][lrow] = av.x;
            As[lk + 1][lrow] = av.y;
            As[lk + 2][lrow] = av.z;
            As[lk + 3][lrow] = av.w;
        }
        // load B tile into Bs[k][n]
        if (TB) {
            int n = n0 + lrow;
            float4 bv = make_float4(0.f, 0.f, 0.f, 0.f);
            if (n < N) bv = *(const float4*)(B + (size_t)n * ldb + k0 + lk);
            Bs[lk + 0][lrow] = bv.x;
            Bs[lk + 1][lrow] = bv.y;
            Bs[lk + 2][lrow] = bv.z;
            Bs[lk + 3][lrow] = bv.w;
        } else {
            int bk = tid >> 5;          // 0..7
            int bn = (tid & 31) * 4;    // 0..124
            float4 bv = make_float4(0.f, 0.f, 0.f, 0.f);
            if (n0 + bn < N) bv = *(const float4*)(B + (size_t)(k0 + bk) * ldb + n0 + bn);
            *(float4*)&Bs[bk][bn] = bv;
        }
        __syncthreads();

#pragma unroll
        for (int k = 0; k < GBK; k++) {
            float a[8], b[8];
            float4 t;
            t = *(const float4*)&As[k][ti * 8];     a[0]=t.x; a[1]=t.y; a[2]=t.z; a[3]=t.w;
            t = *(const float4*)&As[k][ti * 8 + 4]; a[4]=t.x; a[5]=t.y; a[6]=t.z; a[7]=t.w;
            t = *(const float4*)&Bs[k][tj * 8];     b[0]=t.x; b[1]=t.y; b[2]=t.z; b[3]=t.w;
            t = *(const float4*)&Bs[k][tj * 8 + 4]; b[4]=t.x; b[5]=t.y; b[6]=t.z; b[7]=t.w;
#pragma unroll
            for (int i = 0; i < 8; i++)
#pragma unroll
                for (int j = 0; j < 8; j++)
                    acc[i][j] = fmaf(a[i], b[j], acc[i][j]);
        }
        __syncthreads();
    }

#pragma unroll
    for (int i = 0; i < 8; i++) {
        int m = m0 + ti * 8 + i;
        float* cp = C + (size_t)m * ldc + n0 + tj * 8;
#pragma unroll
        for (int j = 0; j < 8; j += 4) {
            if (n0 + tj * 8 + j < N) {
                float4 v = make_float4(acc[i][j], acc[i][j+1], acc[i][j+2], acc[i][j+3]);
                *(float4*)(cp + j) = v;
            }
        }
    }
}

// ---------------- RMSNorm (in-place, one block per row) ----------------
__global__ __launch_bounds__(256) void rmsnorm_kernel(
    float* __restrict__ x, const float* __restrict__ w, int L)
{
    __shared__ float sbuf[8];
    int row = blockIdx.x;
    float* xr = x + (size_t)row * L;
    float ss = 0.f;
    for (int i = threadIdx.x; i < L; i += 256) { float v = xr[i]; ss += v * v; }
#pragma unroll
    for (int o = 16; o; o >>= 1) ss += __shfl_xor_sync(0xffffffffu, ss, o);
    int warp = threadIdx.x >> 5, lane = threadIdx.x & 31;
    if (lane == 0) sbuf[warp] = ss;
    __syncthreads();
    if (threadIdx.x == 0) {
        float t = 0.f;
#pragma unroll
        for (int i = 0; i < 8; i++) t += sbuf[i];
        sbuf[0] = rsqrtf(t / (float)L + EPSc);
    }
    __syncthreads();
    float sc = sbuf[0];
    for (int i = threadIdx.x; i < L; i += 256) xr[i] = xr[i] * sc * w[i];
}

// ---------------- kv split: rmsnorm(latent) + rope(k_pe) -> kfull ----------------
__global__ __launch_bounds__(256) void kvprep_kernel(
    const float* __restrict__ kv, const float* __restrict__ w,
    const float* __restrict__ fcos, const float* __restrict__ fsin,
    float* __restrict__ kfull)
{
    __shared__ float sbuf[8];
    int row = blockIdx.x;
    int s = row & (Ss - 1);
    const float* kr = kv + (size_t)row * DF;
    float* kf = kfull + (size_t)row * DF;

    float ss = 0.f;
    for (int i = threadIdx.x; i < KVLORA; i += 256) { float v = kr[i]; ss += v * v; }
#pragma unroll
    for (int o = 16; o; o >>= 1) ss += __shfl_xor_sync(0xffffffffu, ss, o);
    int warp = threadIdx.x >> 5, lane = threadIdx.x & 31;
    if (lane == 0) sbuf[warp] = ss;
    __syncthreads();
    if (threadIdx.x == 0) {
        float t = 0.f;
#pragma unroll
        for (int i = 0; i < 8; i++) t += sbuf[i];
        sbuf[0] = rsqrtf(t / (float)KVLORA + EPSc);
    }
    __syncthreads();
    float sc = sbuf[0];
    for (int i = threadIdx.x; i < KVLORA; i += 256) kf[i] = kr[i] * sc * w[i];

    if (threadIdx.x < 32) {
        int i = threadIdx.x;
        float x0 = kr[KVLORA + 2 * i], x1 = kr[KVLORA + 2 * i + 1];
        float c = fcos[s * 32 + i], sn = fsin[s * 32 + i];
        kf[KVLORA + 2 * i]     = x0 * c - x1 * sn;
        kf[KVLORA + 2 * i + 1] = x0 * sn + x1 * c;
    }
}

// ---------------- rope(q_pe) -> qfull[:, :, 512:576] ----------------
__global__ __launch_bounds__(512) void ropeq_kernel(
    const float* __restrict__ q, const float* __restrict__ fcos,
    const float* __restrict__ fsin, float* __restrict__ qfull)
{
    int row = blockIdx.x;
    int s = row & (Ss - 1);
    int t = threadIdx.x;       // 512 = 16 heads * 32 pairs
    int h = t >> 5, i = t & 31;
    const float* qr = q + (size_t)row * (Hh * QKH) + h * QKH + NOPEc;
    float x0 = qr[2 * i], x1 = qr[2 * i + 1];
    float c = fcos[s * 32 + i], sn = fsin[s * 32 + i];
    float* dst = qfull + ((size_t)row * Hh + h) * DF + KVLORA;
    dst[2 * i]     = x0 * c - x1 * sn;
    dst[2 * i + 1] = x0 * sn + x1 * c;
}

// ---------------- flash attention (32q x 32k tiles, fp32) ----------------
#define KSTR 577
#define ATTN_SMEM_BYTES ((64 * KSTR + 32 * 33 + 64) * 4)

__global__ __launch_bounds__(256, 1) void attn_kernel(
    const float* __restrict__ qfull, const float* __restrict__ kfull,
    float* __restrict__ ctx)
{
    extern __shared__ float sm[];
    float* Qs   = sm;                 // 32 x 577
    float* Ks   = sm + 32 * KSTR;     // 32 x 577
    float* Ps   = Ks + 32 * KSTR;     // 32 x 33
    float* arow = Ps + 32 * 33;       // 32
    float* lrow = arow + 32;          // 32

    int tid = threadIdx.x;
    int lane = tid & 31, warp = tid >> 5;
    int rg = tid >> 6, cg = tid & 63;        // O-tile: rows rg*8.., cols cg + 64*vv
    int bh = blockIdx.y;
    int b = bh >> 4, h = bh & 15;
    int s0 = blockIdx.x * 32;

    // load Q tile once
    for (int idx = tid; idx < 32 * DF; idx += 256) {
        int i = idx / DF, d = idx - i * DF;
        Qs[i * KSTR + d] = qfull[((size_t)(b * Ss + s0 + i) * Hh + h) * DF + d];
    }

    float acc[8][8];
#pragma unroll
    for (int i = 0; i < 8; i++)
#pragma unroll
        for (int j = 0; j < 8; j++) acc[i][j] = 0.f;

    float mreg[4], lreg[4];
#pragma unroll
    for (int ii = 0; ii < 4; ii++) { mreg[ii] = -INFINITY; lreg[ii] = 0.f; }

    int ntiles = s0 / 32 + 1;
    for (int kt = 0; kt < ntiles; kt++) {
        int t0 = kt * 32;
        // load K tile
        for (int idx = tid; idx < 32 * DF; idx += 256) {
            int j = idx / DF, d = idx - j * DF;
            Ks[j * KSTR + d] = kfull[(size_t)(b * Ss + t0 + j) * DF + d];
        }
        __syncthreads();

        // ---- scores: warp owns rows 4*warp..4*warp+3, lane = key j ----
        {
            const float* kp = Ks + lane * KSTR;
            const float* q0 = Qs + (warp * 4 + 0) * KSTR;
            const float* q1 = q0 + KSTR;
            const float* q2 = q1 + KSTR;
            const float* q3 = q2 + KSTR;
            float sA = 0.f, sB = 0.f, sC = 0.f, sD = 0.f;
#pragma unroll 4
            for (int k = 0; k < DF; k++) {
                float kv = kp[k];
                sA = fmaf(q0[k], kv, sA);
                sB = fmaf(q1[k], kv, sB);
                sC = fmaf(q2[k], kv, sC);
                sD = fmaf(q3[k], kv, sD);
            }
            float scv[4] = {sA, sB, sC, sD};
#pragma unroll
            for (int ii = 0; ii < 4; ii++) {
                int i = warp * 4 + ii;
                float v = scv[ii] * SCALEc;
                if (t0 + lane > s0 + i) v = -INFINITY;   // causal mask
                float mx = v;
#pragma unroll
                for (int o = 16; o; o >>= 1) mx = fmaxf(mx, __shfl_xor_sync(0xffffffffu, mx, o));
                float mnew = fmaxf(mreg[ii], mx);
                float p = __expf(v - mnew);
                float psum = p;
#pragma unroll
                for (int o = 16; o; o >>= 1) psum += __shfl_xor_sync(0xffffffffu, psum, o);
                float al = __expf(mreg[ii] - mnew);
                lreg[ii] = lreg[ii] * al + psum;
                mreg[ii] = mnew;
                Ps[i * 33 + lane] = p;
                if (lane == 0) arow[i] = al;
            }
        }
        __syncthreads();

        // ---- O update: acc = alpha*acc + P @ V (V = Ks[:, :512]) ----
        {
            float al[8];
#pragma unroll
            for (int ii = 0; ii < 8; ii++) al[ii] = arow[rg * 8 + ii];
#pragma unroll
            for (int ii = 0; ii < 8; ii++)
#pragma unroll
                for (int vv = 0; vv < 8; vv++) acc[ii][vv] *= al[ii];

            for (int j = 0; j < 32; j++) {
                float v[8], p[8];
#pragma unroll
                for (int vv = 0; vv < 8; vv++) v[vv] = Ks[j * KSTR + cg + vv * 64];
#pragma unroll
                for (int ii = 0; ii < 8; ii++) p[ii] = Ps[(rg * 8 + ii) * 33 + j];
#pragma unroll
                for (int ii = 0; ii < 8; ii++)
#pragma unroll
                    for (int vv = 0; vv < 8; vv++)
                        acc[ii][vv] = fmaf(p[ii], v[vv], acc[ii][vv]);
            }
        }
        __syncthreads();
    }

    // publish l, normalize, store ctx
    if (lane == 0) {
#pragma unroll
        for (int ii = 0; ii < 4; ii++) lrow[warp * 4 + ii] = lreg[ii];
    }
    __syncthreads();
#pragma unroll
    for (int ii = 0; ii < 8; ii++) {
        int i = rg * 8 + ii;
        float inv = 1.0f / lrow[i];
        float* cp = ctx + ((size_t)(b * Ss + s0 + i) * Hh + h) * KVLORA + cg;
#pragma unroll
        for (int vv = 0; vv < 8; vv++) cp[vv * 64] = acc[ii][vv] * inv;
    }
}

// ---------------- launch ----------------
extern "C" void kernel_launch(void* const* d_in, const int* in_sizes, int n_in,
                              void* d_out, int out_size)
{
    const float* x     = (const float*)d_in[0];
    const float* fcos  = (const float*)d_in[1];
    const float* fsin  = (const float*)d_in[2];
    // d_in[3] = mask (causal; handled analytically)
    const float* wq_a  = (const float*)d_in[4];
    const float* q_ln  = (const float*)d_in[5];
    const float* wq_b  = (const float*)d_in[6];
    const float* wkv_a = (const float*)d_in[7];
    const float* kv_ln = (const float*)d_in[8];
    const float* wkv_b = (const float*)d_in[9];
    const float* wo    = (const float*)d_in[10];
    float* out = (float*)d_out;

    float *qlat, *q, *kv, *kfull, *qfull, *ctx, *attnout;
    cudaGetSymbolAddress((void**)&qlat,    g_qlat);
    cudaGetSymbolAddress((void**)&q,       g_q);
    cudaGetSymbolAddress((void**)&kv,      g_kv);
    cudaGetSymbolAddress((void**)&kfull,   g_kfull);
    cudaGetSymbolAddress((void**)&qfull,   g_qfull);
    cudaGetSymbolAddress((void**)&ctx,     g_ctx);
    cudaGetSymbolAddress((void**)&attnout, g_attnout);

    dim3 blk(256);

    // 1. q_lat_pre = x @ wq_a^T      (4096 x 1536, K=2048)
    gemm_kernel<true><<<dim3(QLORA / GBN, ROWS / GBM, 1), blk>>>(
        x, DIMc, 0, wq_a, DIMc, 0, qlat, QLORA, 0, ROWS, QLORA, DIMc);

    // 2. rmsnorm in place
    rmsnorm_kernel<<<ROWS, 256>>>(qlat, q_ln, QLORA);

    // 3. q = q_lat @ wq_b^T          (4096 x 3072, K=1536)
    gemm_kernel<true><<<dim3((Hh * QKH) / GBN, ROWS / GBM, 1), blk>>>(
        qlat, QLORA, 0, wq_b, QLORA, 0, q, Hh * QKH, 0, ROWS, Hh * QKH, QLORA);

    // 4. kv = x @ wkv_a^T            (4096 x 576, K=2048)
    gemm_kernel<true><<<dim3((DF + GBN - 1) / GBN, ROWS / GBM, 1), blk>>>(
        x, DIMc, 0, wkv_a, DIMc, 0, kv, DF, 0, ROWS, DF, DIMc);

    // 5. kfull = [rmsnorm(kv_lat), rope(k_pe)]
    kvprep_kernel<<<ROWS, 256>>>(kv, kv_ln, fcos, fsin, kfull);

    // 6. q-absorb per head: qfull[:, h, :512] = q_nope_h @ wkv_b3[h, :128, :]  (NN, batched over 16 heads)
    gemm_kernel<false><<<dim3(KVLORA / GBN, ROWS / GBM, Hh), blk>>>(
        q, Hh * QKH, QKH,
        wkv_b, KVLORA, (long)(NOPEc + VDIMc) * KVLORA,
        qfull, Hh * DF, DF,
        ROWS, KVLORA, NOPEc);

    // 7. qfull[:, h, 512:576] = rope(q_pe)
    ropeq_kernel<<<ROWS, 512>>>(q, fcos, fsin, qfull);

    // 8. flash attention -> ctx (B,S,H,512)
    cudaFuncSetAttribute(attn_kernel, cudaFuncAttributeMaxDynamicSharedMemorySize,
                         ATTN_SMEM_BYTES);
    attn_kernel<<<dim3(Ss / 32, Bb * Hh), 256, ATTN_SMEM_BYTES>>>(qfull, kfull, ctx);

    // 9. per-head out-proj: attnout[:, h*128:(h+1)*128] = ctx_h @ wkv_b3[h, 128:256, :]^T (TN, batched)
    gemm_kernel<true><<<dim3(VDIMc / GBN + (VDIMc % GBN != 0), ROWS / GBM, Hh), blk>>>(
        ctx, Hh * KVLORA, KVLORA,
        wkv_b + (size_t)NOPEc * KVLORA, KVLORA, (long)(NOPEc + VDIMc) * KVLORA,
        attnout, DIMc, VDIMc,
        ROWS, VDIMc, KVLORA);

    // 10. out = attnout @ wo^T       (4096 x 2048, K=2048)
    gemm_kernel<true><<<dim3(DIMc / GBN, ROWS / GBM, 1), blk>>>(
        attnout, DIMc, 0, wo, DIMc, 0, out, DIMc, 0, ROWS, DIMc, DIMc);
}